// round 15
// baseline (speedup 1.0000x reference)
#include <cuda_runtime.h>
#include <cuda_bf16.h>
#include <cuda_fp16.h>
#include <cstdint>
#include <cstddef>

#define BB 4
#define CCH 256
#define CQ 32
#define NT 4096

// ---- scratch (device globals; no allocation allowed) ----
__device__ __half g_f[BB * NT * CQ];                     // [b][n][o] (queries, fp16)
__device__ __half g_g[BB * NT * CQ];                     // [b][n][o] (keys, fp16)
__device__ __nv_bfloat16 g_h[(size_t)BB * CCH * NT];     // [b][c][n] (values, bf16)
__device__ int g_flag[BB];                               // proj completion counters (monotonic)

__device__ __forceinline__ void mma_tf32(float* d, const uint32_t* a,
                                         uint32_t b0, uint32_t b1) {
    asm volatile(
        "mma.sync.aligned.m16n8k8.row.col.f32.tf32.tf32.f32 "
        "{%0,%1,%2,%3}, {%4,%5,%6,%7}, {%8,%9}, {%0,%1,%2,%3};"
        : "+f"(d[0]), "+f"(d[1]), "+f"(d[2]), "+f"(d[3])
        : "r"(a[0]), "r"(a[1]), "r"(a[2]), "r"(a[3]), "r"(b0), "r"(b1));
}
__device__ __forceinline__ void mma_f16(float* d, const uint32_t* a,
                                        uint32_t b0, uint32_t b1) {
    asm volatile(
        "mma.sync.aligned.m16n8k16.row.col.f32.f16.f16.f32 "
        "{%0,%1,%2,%3}, {%4,%5,%6,%7}, {%8,%9}, {%0,%1,%2,%3};"
        : "+f"(d[0]), "+f"(d[1]), "+f"(d[2]), "+f"(d[3])
        : "r"(a[0]), "r"(a[1]), "r"(a[2]), "r"(a[3]), "r"(b0), "r"(b1));
}
__device__ __forceinline__ void mma_bf16(float* d, const uint32_t* a,
                                         uint32_t b0, uint32_t b1) {
    asm volatile(
        "mma.sync.aligned.m16n8k16.row.col.f32.bf16.bf16.f32 "
        "{%0,%1,%2,%3}, {%4,%5,%6,%7}, {%8,%9}, {%0,%1,%2,%3};"
        : "+f"(d[0]), "+f"(d[1]), "+f"(d[2]), "+f"(d[3])
        : "r"(a[0]), "r"(a[1]), "r"(a[2]), "r"(a[3]), "r"(b0), "r"(b1));
}
#define LDMX4(r, addr) \
    asm volatile("ldmatrix.sync.aligned.m8n8.x4.shared.b16 {%0,%1,%2,%3}, [%4];" \
        : "=r"((r)[0]), "=r"((r)[1]), "=r"((r)[2]), "=r"((r)[3]) : "r"(addr))

__device__ __forceinline__ uint32_t smem_u32(const void* p) {
    uint32_t a;
    asm("{ .reg .u64 t; cvta.to.shared.u64 t, %1; cvt.u32.u64 %0, t; }" : "=r"(a) : "l"(p));
    return a;
}
__device__ __forceinline__ void cpa(uint32_t dst, const void* src) {
    asm volatile("cp.async.cg.shared.global [%0], [%1], 16;" :: "r"(dst), "l"(src));
}
#define CP_COMMIT() asm volatile("cp.async.commit_group;" ::: "memory")
#define CP_WAIT1()  asm volatile("cp.async.wait_group 1;" ::: "memory")
#define CP_WAIT0()  asm volatile("cp.async.wait_group 0;" ::: "memory")

// ---- proj geometry ----
#define XP  136
#define WPD 36
#define XS_BUF (32 * XP * 4)
#define OFF_WS (2 * XS_BUF)
#define WS_BUF (64 * WPD * 4)
#define SMEM_PROJ (OFF_WS + 2 * WS_BUF)

// ---- attn geometry ----
#define VTP 72
#define KPH 40
#define PP  72
#define OFF_VT 0
#define VT_BUF 36864
#define OFF_KS 73728
#define KS_BUF 5120
#define OFF_PS (OFF_KS + 3 * KS_BUF)
#define OFF_RS (OFF_PS + 9216)
#define SMEM_ATTN (OFF_RS + 512)

#define PROJ_BLOCKS 640
#define PROJ_PER_B  160
#define ATTN_PER_B  64

// ============================================================
// proj body: identical math to R12's proj_kernel
// ============================================================
__device__ void proj_body(
    char* smc,
    const float* __restrict__ x,
    const float* __restrict__ Wf, const float* __restrict__ bf,
    const float* __restrict__ Wg, const float* __restrict__ bg,
    const float* __restrict__ Wh, const float* __restrict__ bh,
    int b, int rowbase, int n0)
{
    const uint32_t sb32 = smem_u32(smc);
    const int tid = threadIdx.x;
    const int w = tid >> 5, lane = tid & 31;
    const int g = lane >> 2, t4 = lane & 3;
    const int qr = (w & 3) * 16;
    const int nh = (w >> 2) * 64;

    {
        const uint32_t XA = sb32;
        const uint32_t WA = sb32 + OFF_WS;
#pragma unroll
        for (int it = 0; it < 4; it++) {
            int idx = tid + it * 256;
            int k = idx >> 5, nn = (idx & 31) * 4;
            cpa(XA + (k * XP + nn) * 4, x + ((size_t)b * CCH + k) * NT + n0 + nn);
        }
#pragma unroll
        for (int it = 0; it < 2; it++) {
            int idx = tid + it * 256;
            int m = idx >> 3, kk = (idx & 7) * 4;
            int rg = rowbase + m;
            const float* src;
            if (rg < 32)       src = Wf + rg * CCH;
            else if (rg < 64)  src = Wg + (rg - 32) * CCH;
            else               src = Wh + (rg - 64) * CCH;
            cpa(WA + (m * WPD + kk) * 4, src + kk);
        }
        CP_COMMIT();
    }

    float acc[8][4];
#pragma unroll
    for (int nf = 0; nf < 8; nf++)
#pragma unroll
        for (int r = 0; r < 4; r++) acc[nf][r] = 0.f;

#pragma unroll 1
    for (int c = 0; c < 8; c++) {
        __syncthreads();
        if (c + 1 < 8) {
            const int k0 = (c + 1) * 32;
            const uint32_t XA = sb32 + ((c + 1) & 1) * XS_BUF;
            const uint32_t WA = sb32 + OFF_WS + ((c + 1) & 1) * WS_BUF;
#pragma unroll
            for (int it = 0; it < 4; it++) {
                int idx = tid + it * 256;
                int k = idx >> 5, nn = (idx & 31) * 4;
                cpa(XA + (k * XP + nn) * 4, x + ((size_t)b * CCH + k0 + k) * NT + n0 + nn);
            }
#pragma unroll
            for (int it = 0; it < 2; it++) {
                int idx = tid + it * 256;
                int m = idx >> 3, kk = (idx & 7) * 4;
                int rg = rowbase + m;
                const float* src;
                if (rg < 32)       src = Wf + rg * CCH;
                else if (rg < 64)  src = Wg + (rg - 32) * CCH;
                else               src = Wh + (rg - 64) * CCH;
                cpa(WA + (m * WPD + kk) * 4, src + k0 + kk);
            }
            CP_COMMIT();
            CP_WAIT1();
        } else {
            CP_WAIT0();
        }
        __syncthreads();

        const float* Xb = (const float*)(smc + (c & 1) * XS_BUF);
        const float* Wb = (const float*)(smc + OFF_WS + (c & 1) * WS_BUF);
#pragma unroll
        for (int kc = 0; kc < 4; kc++) {
            uint32_t A[4];
            A[0] = __float_as_uint(Wb[(qr + g) * WPD + kc * 8 + t4]);
            A[1] = __float_as_uint(Wb[(qr + 8 + g) * WPD + kc * 8 + t4]);
            A[2] = __float_as_uint(Wb[(qr + g) * WPD + kc * 8 + t4 + 4]);
            A[3] = __float_as_uint(Wb[(qr + 8 + g) * WPD + kc * 8 + t4 + 4]);
#pragma unroll
            for (int nf = 0; nf < 8; nf++) {
                uint32_t b0 = __float_as_uint(Xb[(kc * 8 + t4) * XP + nh + nf * 8 + g]);
                uint32_t b1 = __float_as_uint(Xb[(kc * 8 + t4 + 4) * XP + nh + nf * 8 + g]);
                mma_tf32(acc[nf], A, b0, b1);
            }
        }
    }

    if (rowbase == 0) {
        const bool isf = (qr < 32);
        __half* dst = isf ? g_f : g_g;
        const float* bias = isf ? bf : bg;
        const int ob = isf ? qr : qr - 32;
        float bia0 = bias[ob + g], bia1 = bias[ob + 8 + g];
#pragma unroll
        for (int nf = 0; nf < 8; nf++) {
            int n = n0 + nh + nf * 8 + 2 * t4;
            size_t base0 = ((size_t)b * NT + n) * CQ;
            dst[base0 + ob + g]          = __float2half_rn(acc[nf][0] + bia0);
            dst[base0 + CQ + ob + g]     = __float2half_rn(acc[nf][1] + bia0);
            dst[base0 + ob + 8 + g]      = __float2half_rn(acc[nf][2] + bia1);
            dst[base0 + CQ + ob + 8 + g] = __float2half_rn(acc[nf][3] + bia1);
        }
    } else {
        int c0 = rowbase - 64 + qr + g;
        float bia0 = bh[c0], bia1 = bh[c0 + 8];
#pragma unroll
        for (int nf = 0; nf < 8; nf++) {
            int n = n0 + nh + nf * 8 + 2 * t4;
            __nv_bfloat162 v0 = __floats2bfloat162_rn(acc[nf][0] + bia0, acc[nf][1] + bia0);
            __nv_bfloat162 v1 = __floats2bfloat162_rn(acc[nf][2] + bia1, acc[nf][3] + bia1);
            *(__nv_bfloat162*)&g_h[((size_t)b * CCH + c0) * NT + n] = v0;
            *(__nv_bfloat162*)&g_h[((size_t)b * CCH + c0 + 8) * NT + n] = v1;
        }
    }

    // release: this proj CTA's outputs are visible before the flag increment
    __threadfence();
    __syncthreads();
    if (threadIdx.x == 0) atomicAdd(&g_flag[b], 1);
}

// ============================================================
// attn body: identical math to R12's attn_kernel
// ============================================================
__device__ void attn_body(
    char* smc,
    const float* __restrict__ x, const float* __restrict__ gammap,
    float* __restrict__ out, int b, int m0)
{
    const uint32_t sb32 = smem_u32(smc);
    const int tid = threadIdx.x;
    const int w = tid >> 5, lane = tid & 31;
    const int g = lane >> 2, t = lane & 3;

    const int qrow  = (w & 3) * 16;
    const int khalf = (w >> 2);
    const int mr0 = (w >> 2) * 32;
    const int cr  = (w & 3) * 64;

    const int a_row  = lane & 15;
    const int a_koff = (lane >> 4) * 8;
    const int b_c    = ((lane >> 4) & 1) * 8 + (lane & 7);
    const int b_koff = ((lane >> 3) & 1) * 8;

    // acquire: wait for all 160 proj CTAs of this batch (monotonic; stale-fast
    // path on graph replays reads identical re-written data — benign)
    if (tid == 0) {
        while (*(volatile int*)&g_flag[b] < PROJ_PER_B) { __nanosleep(64); }
        __threadfence();
    }
    __syncthreads();

    uint32_t qa[2][4];
    {
        const __half* q = g_f + ((size_t)b * NT + m0 + qrow) * CQ;
#pragma unroll
        for (int kc = 0; kc < 2; kc++) {
            qa[kc][0] = *(const uint32_t*)&q[(size_t)g * CQ + kc * 16 + 2 * t];
            qa[kc][1] = *(const uint32_t*)&q[(size_t)(g + 8) * CQ + kc * 16 + 2 * t];
            qa[kc][2] = *(const uint32_t*)&q[(size_t)g * CQ + kc * 16 + 2 * t + 8];
            qa[kc][3] = *(const uint32_t*)&q[(size_t)(g + 8) * CQ + kc * 16 + 2 * t + 8];
        }
    }

    const __half* kg = g_g + (size_t)b * NT * CQ;
    const __nv_bfloat16* vg = g_h + (size_t)b * CCH * NT;
    const int krow = tid >> 2, kseg = tid & 3;

    {
        cpa(sb32 + OFF_KS + krow * (KPH * 2) + kseg * 16,
            kg + (size_t)krow * CQ + kseg * 8);
        cpa(sb32 + OFF_KS + KS_BUF + krow * (KPH * 2) + kseg * 16,
            kg + (size_t)(64 + krow) * CQ + kseg * 8);
#pragma unroll
        for (int it = 0; it < 8; it++) {
            int idx = tid + it * 256;
            int c = idx >> 3, ch = idx & 7;
            cpa(sb32 + OFF_VT + (c * VTP + ch * 8) * 2, vg + (size_t)c * NT + ch * 8);
        }
        CP_COMMIT();
    }

    float acc[2][8][4];
#pragma unroll
    for (int mt = 0; mt < 2; mt++)
#pragma unroll
        for (int nt = 0; nt < 8; nt++)
#pragma unroll
            for (int r = 0; r < 4; r++) acc[mt][nt][r] = 0.f;
    float rsum0 = 0.f, rsum1 = 0.f;
    float s[4][4];

    CP_WAIT0();
    __syncthreads();

    {
        const __half* Ks = (const __half*)(smc + OFF_KS);
#pragma unroll
        for (int nt = 0; nt < 4; nt++) {
#pragma unroll
            for (int r = 0; r < 4; r++) s[nt][r] = 0.f;
            const __half* kr = Ks + (khalf * 32 + nt * 8 + g) * KPH;
#pragma unroll
            for (int kc = 0; kc < 2; kc++) {
                uint32_t b0 = *(const uint32_t*)&kr[kc * 16 + 2 * t];
                uint32_t b1 = *(const uint32_t*)&kr[kc * 16 + 2 * t + 8];
                mma_f16(s[nt], qa[kc], b0, b1);
            }
        }
    }

#pragma unroll 1
    for (int kt = 0; kt < 64; kt++) {
        const int buf = kt & 1;
        __syncthreads();   // B1

        if (kt + 1 < 64) {
            const int n0 = (kt + 1) * 64;
            const uint32_t VA = sb32 + OFF_VT + (1 - buf) * VT_BUF;
#pragma unroll
            for (int it = 0; it < 8; it++) {
                int idx = tid + it * 256;
                int c = idx >> 3, ch = idx & 7;
                cpa(VA + (c * VTP + ch * 8) * 2, vg + (size_t)c * NT + n0 + ch * 8);
            }
        }
        if (kt + 2 < 64) {
            const uint32_t KA = sb32 + OFF_KS + ((kt + 2) % 3) * KS_BUF;
            cpa(KA + krow * (KPH * 2) + kseg * 16,
                kg + (size_t)((kt + 2) * 64 + krow) * CQ + kseg * 8);
        }
        CP_COMMIT();

        {
            __nv_bfloat16* Ps = (__nv_bfloat16*)(smc + OFF_PS);
#pragma unroll
            for (int nt = 0; nt < 4; nt++) {
                float p0 = __expf(s[nt][0]);
                float p1 = __expf(s[nt][1]);
                float p2 = __expf(s[nt][2]);
                float p3 = __expf(s[nt][3]);
                rsum0 += p0 + p1;
                rsum1 += p2 + p3;
                int col = khalf * 32 + nt * 8 + 2 * t;
                *(__nv_bfloat162*)&Ps[(qrow + g) * PP + col] = __floats2bfloat162_rn(p0, p1);
                *(__nv_bfloat162*)&Ps[(qrow + 8 + g) * PP + col] = __floats2bfloat162_rn(p2, p3);
            }
        }

        CP_WAIT1();
        __syncthreads();   // B2

        if (kt + 1 < 64) {
            const __half* Ks = (const __half*)(smc + OFF_KS + ((kt + 1) % 3) * KS_BUF);
#pragma unroll
            for (int nt = 0; nt < 4; nt++) {
#pragma unroll
                for (int r = 0; r < 4; r++) s[nt][r] = 0.f;
                const __half* kr = Ks + (khalf * 32 + nt * 8 + g) * KPH;
#pragma unroll
                for (int kc = 0; kc < 2; kc++) {
                    uint32_t b0 = *(const uint32_t*)&kr[kc * 16 + 2 * t];
                    uint32_t b1 = *(const uint32_t*)&kr[kc * 16 + 2 * t + 8];
                    mma_f16(s[nt], qa[kc], b0, b1);
                }
            }
        }

        const uint32_t PA = sb32 + OFF_PS;
        const uint32_t VA = sb32 + OFF_VT + buf * VT_BUF;
#pragma unroll
        for (int kc = 0; kc < 4; kc++) {
            uint32_t A0[4], A1[4];
            LDMX4(A0, PA + ((mr0 + a_row) * PP + kc * 16 + a_koff) * 2);
            LDMX4(A1, PA + ((mr0 + 16 + a_row) * PP + kc * 16 + a_koff) * 2);
#pragma unroll
            for (int np = 0; np < 4; np++) {
                uint32_t Bf[4];
                LDMX4(Bf, VA + ((cr + np * 16 + b_c) * VTP + kc * 16 + b_koff) * 2);
                mma_bf16(acc[0][np * 2],     A0, Bf[0], Bf[1]);
                mma_bf16(acc[0][np * 2 + 1], A0, Bf[2], Bf[3]);
                mma_bf16(acc[1][np * 2],     A1, Bf[0], Bf[1]);
                mma_bf16(acc[1][np * 2 + 1], A1, Bf[2], Bf[3]);
            }
        }
    }

    rsum0 += __shfl_xor_sync(0xffffffffu, rsum0, 1);
    rsum0 += __shfl_xor_sync(0xffffffffu, rsum0, 2);
    rsum1 += __shfl_xor_sync(0xffffffffu, rsum1, 1);
    rsum1 += __shfl_xor_sync(0xffffffffu, rsum1, 2);
    float* rs = (float*)(smc + OFF_RS);
    __syncthreads();
    if (t == 0) {
        rs[khalf * 64 + qrow + g] = rsum0;
        rs[khalf * 64 + qrow + 8 + g] = rsum1;
    }
    __syncthreads();

    const float gamma = gammap[0];
#pragma unroll
    for (int mt = 0; mt < 2; mt++) {
        int rg  = mr0 + mt * 16 + g;
        int rg8 = rg + 8;
        float s0 = gamma / (rs[rg]  + rs[64 + rg]);
        float s8 = gamma / (rs[rg8] + rs[64 + rg8]);
#pragma unroll
        for (int nt = 0; nt < 8; nt++) {
            int c = cr + nt * 8 + 2 * t;
            size_t gi0 = ((size_t)b * CCH + c) * NT + m0 + rg;
            size_t gi1 = gi0 + NT;
            size_t gj0 = ((size_t)b * CCH + c) * NT + m0 + rg8;
            size_t gj1 = gj0 + NT;
            out[gi0] = acc[mt][nt][0] * s0 + x[gi0];
            out[gi1] = acc[mt][nt][1] * s0 + x[gi1];
            out[gj0] = acc[mt][nt][2] * s8 + x[gj0];
            out[gj1] = acc[mt][nt][3] * s8 + x[gj1];
        }
    }
}

// ============================================================
// Fused kernel: bids [0,640) proj (batch-major), [640,896) attn.
// ============================================================
__global__ __launch_bounds__(256, 2) void fused_kernel(
    const float* __restrict__ x,
    const float* __restrict__ Wf, const float* __restrict__ bf,
    const float* __restrict__ Wg, const float* __restrict__ bg,
    const float* __restrict__ Wh, const float* __restrict__ bh,
    const float* __restrict__ gammap, float* __restrict__ out)
{
    extern __shared__ char smc[];
    const int bid = blockIdx.x;
    if (bid < PROJ_BLOCKS) {
        const int b = bid / PROJ_PER_B;
        const int r = bid % PROJ_PER_B;
        proj_body(smc, x, Wf, bf, Wg, bg, Wh, bh, b, (r / 32) * 64, (r % 32) * 128);
    } else {
        const int ab = bid - PROJ_BLOCKS;
        const int b = ab / ATTN_PER_B;
        const int m0 = (ab % ATTN_PER_B) * 64;
        attn_body(smc, x, gammap, out, b, m0);
    }
}

// ============================================================
extern "C" void kernel_launch(void* const* d_in, const int* in_sizes, int n_in,
                              void* d_out, int out_size)
{
    const float* x  = (const float*)d_in[0];
    const float* Wf = (const float*)d_in[1];
    const float* bf = (const float*)d_in[2];
    const float* Wg = (const float*)d_in[3];
    const float* bg = (const float*)d_in[4];
    const float* Wh = (const float*)d_in[5];
    const float* bh = (const float*)d_in[6];
    const float* gm = (const float*)d_in[7];
    float* out = (float*)d_out;

    cudaFuncSetAttribute(fused_kernel, cudaFuncAttributeMaxDynamicSharedMemorySize, SMEM_ATTN);
    fused_kernel<<<PROJ_BLOCKS + BB * ATTN_PER_B, 256, SMEM_ATTN>>>(
        x, Wf, bf, Wg, bg, Wh, bh, gm, out);
}

// round 16
// speedup vs baseline: 1.0220x; 1.0220x over previous
#include <cuda_runtime.h>
#include <cuda_bf16.h>
#include <cuda_fp16.h>
#include <cstdint>
#include <cstddef>

#define BB 4
#define CCH 256
#define CQ 32
#define NT 4096

// ---- scratch (device globals; no allocation allowed) ----
__device__ __half g_f[BB * NT * CQ];                     // [b][n][o] (queries, fp16)
__device__ __half g_g[BB * NT * CQ];                     // [b][n][o] (keys, fp16)
__device__ __nv_bfloat16 g_h[(size_t)BB * CCH * NT];     // [b][c][n] (values, bf16)

__device__ __forceinline__ void mma_tf32(float* d, const uint32_t* a,
                                         uint32_t b0, uint32_t b1) {
    asm volatile(
        "mma.sync.aligned.m16n8k8.row.col.f32.tf32.tf32.f32 "
        "{%0,%1,%2,%3}, {%4,%5,%6,%7}, {%8,%9}, {%0,%1,%2,%3};"
        : "+f"(d[0]), "+f"(d[1]), "+f"(d[2]), "+f"(d[3])
        : "r"(a[0]), "r"(a[1]), "r"(a[2]), "r"(a[3]), "r"(b0), "r"(b1));
}
__device__ __forceinline__ void mma_f16(float* d, const uint32_t* a,
                                        uint32_t b0, uint32_t b1) {
    asm volatile(
        "mma.sync.aligned.m16n8k16.row.col.f32.f16.f16.f32 "
        "{%0,%1,%2,%3}, {%4,%5,%6,%7}, {%8,%9}, {%0,%1,%2,%3};"
        : "+f"(d[0]), "+f"(d[1]), "+f"(d[2]), "+f"(d[3])
        : "r"(a[0]), "r"(a[1]), "r"(a[2]), "r"(a[3]), "r"(b0), "r"(b1));
}
__device__ __forceinline__ void mma_bf16(float* d, const uint32_t* a,
                                         uint32_t b0, uint32_t b1) {
    asm volatile(
        "mma.sync.aligned.m16n8k16.row.col.f32.bf16.bf16.f32 "
        "{%0,%1,%2,%3}, {%4,%5,%6,%7}, {%8,%9}, {%0,%1,%2,%3};"
        : "+f"(d[0]), "+f"(d[1]), "+f"(d[2]), "+f"(d[3])
        : "r"(a[0]), "r"(a[1]), "r"(a[2]), "r"(a[3]), "r"(b0), "r"(b1));
}
#define LDMX4(r, addr) \
    asm volatile("ldmatrix.sync.aligned.m8n8.x4.shared.b16 {%0,%1,%2,%3}, [%4];" \
        : "=r"((r)[0]), "=r"((r)[1]), "=r"((r)[2]), "=r"((r)[3]) : "r"(addr))

__device__ __forceinline__ uint32_t smem_u32(const void* p) {
    uint32_t a;
    asm("{ .reg .u64 t; cvta.to.shared.u64 t, %1; cvt.u32.u64 %0, t; }" : "=r"(a) : "l"(p));
    return a;
}
__device__ __forceinline__ void cpa(uint32_t dst, const void* src) {
    asm volatile("cp.async.cg.shared.global [%0], [%1], 16;" :: "r"(dst), "l"(src));
}
#define CP_COMMIT() asm volatile("cp.async.commit_group;" ::: "memory")
#define CP_WAIT1()  asm volatile("cp.async.wait_group 1;" ::: "memory")
#define CP_WAIT0()  asm volatile("cp.async.wait_group 0;" ::: "memory")

// ============================================================
// Tensor-core projection (tf32 mma), k32 chunks,
// __launch_bounds__(256,4): 64-reg cap -> 4 CTAs/SM (measured ~23.6us).
// grid (NT/128, 5, B) = 640 CTAs.
// ============================================================
#define XP  136
#define WPD 36
#define XS_BUF (32 * XP * 4)
#define OFF_WS (2 * XS_BUF)
#define WS_BUF (64 * WPD * 4)
#define SMEM_PROJ (OFF_WS + 2 * WS_BUF)

__global__ __launch_bounds__(256, 4) void proj_kernel(
    const float* __restrict__ x,
    const float* __restrict__ Wf, const float* __restrict__ bf,
    const float* __restrict__ Wg, const float* __restrict__ bg,
    const float* __restrict__ Wh, const float* __restrict__ bh)
{
    extern __shared__ char smc[];
    const uint32_t sb32 = smem_u32(smc);
    const int tid = threadIdx.x;
    const int w = tid >> 5, lane = tid & 31;
    const int g = lane >> 2, t4 = lane & 3;
    const int b = blockIdx.z;
    const int rowbase = blockIdx.y * 64;
    const int n0 = blockIdx.x * 128;
    const int qr = (w & 3) * 16;
    const int nh = (w >> 2) * 64;

    {
        const uint32_t XA = sb32;
        const uint32_t WA = sb32 + OFF_WS;
#pragma unroll
        for (int it = 0; it < 4; it++) {
            int idx = tid + it * 256;
            int k = idx >> 5, nn = (idx & 31) * 4;
            cpa(XA + (k * XP + nn) * 4, x + ((size_t)b * CCH + k) * NT + n0 + nn);
        }
#pragma unroll
        for (int it = 0; it < 2; it++) {
            int idx = tid + it * 256;
            int m = idx >> 3, kk = (idx & 7) * 4;
            int rg = rowbase + m;
            const float* src;
            if (rg < 32)       src = Wf + rg * CCH;
            else if (rg < 64)  src = Wg + (rg - 32) * CCH;
            else               src = Wh + (rg - 64) * CCH;
            cpa(WA + (m * WPD + kk) * 4, src + kk);
        }
        CP_COMMIT();
    }

    float acc[8][4];
#pragma unroll
    for (int nf = 0; nf < 8; nf++)
#pragma unroll
        for (int r = 0; r < 4; r++) acc[nf][r] = 0.f;

#pragma unroll 1
    for (int c = 0; c < 8; c++) {
        __syncthreads();
        if (c + 1 < 8) {
            const int k0 = (c + 1) * 32;
            const uint32_t XA = sb32 + ((c + 1) & 1) * XS_BUF;
            const uint32_t WA = sb32 + OFF_WS + ((c + 1) & 1) * WS_BUF;
#pragma unroll
            for (int it = 0; it < 4; it++) {
                int idx = tid + it * 256;
                int k = idx >> 5, nn = (idx & 31) * 4;
                cpa(XA + (k * XP + nn) * 4, x + ((size_t)b * CCH + k0 + k) * NT + n0 + nn);
            }
#pragma unroll
            for (int it = 0; it < 2; it++) {
                int idx = tid + it * 256;
                int m = idx >> 3, kk = (idx & 7) * 4;
                int rg = rowbase + m;
                const float* src;
                if (rg < 32)       src = Wf + rg * CCH;
                else if (rg < 64)  src = Wg + (rg - 32) * CCH;
                else               src = Wh + (rg - 64) * CCH;
                cpa(WA + (m * WPD + kk) * 4, src + k0 + kk);
            }
            CP_COMMIT();
            CP_WAIT1();
        } else {
            CP_WAIT0();
        }
        __syncthreads();

        const float* Xb = (const float*)(smc + (c & 1) * XS_BUF);
        const float* Wb = (const float*)(smc + OFF_WS + (c & 1) * WS_BUF);
#pragma unroll
        for (int kc = 0; kc < 4; kc++) {
            uint32_t A[4];
            A[0] = __float_as_uint(Wb[(qr + g) * WPD + kc * 8 + t4]);
            A[1] = __float_as_uint(Wb[(qr + 8 + g) * WPD + kc * 8 + t4]);
            A[2] = __float_as_uint(Wb[(qr + g) * WPD + kc * 8 + t4 + 4]);
            A[3] = __float_as_uint(Wb[(qr + 8 + g) * WPD + kc * 8 + t4 + 4]);
#pragma unroll
            for (int nf = 0; nf < 8; nf++) {
                uint32_t b0 = __float_as_uint(Xb[(kc * 8 + t4) * XP + nh + nf * 8 + g]);
                uint32_t b1 = __float_as_uint(Xb[(kc * 8 + t4 + 4) * XP + nh + nf * 8 + g]);
                mma_tf32(acc[nf], A, b0, b1);
            }
        }
    }

    if (rowbase == 0) {
        const bool isf = (qr < 32);
        __half* dst = isf ? g_f : g_g;
        const float* bias = isf ? bf : bg;
        const int ob = isf ? qr : qr - 32;
        float bia0 = bias[ob + g], bia1 = bias[ob + 8 + g];
#pragma unroll
        for (int nf = 0; nf < 8; nf++) {
            int n = n0 + nh + nf * 8 + 2 * t4;
            size_t base0 = ((size_t)b * NT + n) * CQ;
            dst[base0 + ob + g]          = __float2half_rn(acc[nf][0] + bia0);
            dst[base0 + CQ + ob + g]     = __float2half_rn(acc[nf][1] + bia0);
            dst[base0 + ob + 8 + g]      = __float2half_rn(acc[nf][2] + bia1);
            dst[base0 + CQ + ob + 8 + g] = __float2half_rn(acc[nf][3] + bia1);
        }
    } else {
        int c0 = rowbase - 64 + qr + g;
        float bia0 = bh[c0], bia1 = bh[c0 + 8];
#pragma unroll
        for (int nf = 0; nf < 8; nf++) {
            int n = n0 + nh + nf * 8 + 2 * t4;
            __nv_bfloat162 v0 = __floats2bfloat162_rn(acc[nf][0] + bia0, acc[nf][1] + bia0);
            __nv_bfloat162 v1 = __floats2bfloat162_rn(acc[nf][2] + bia1, acc[nf][3] + bia1);
            *(__nv_bfloat162*)&g_h[((size_t)b * CCH + c0) * NT + n] = v0;
            *(__nv_bfloat162*)&g_h[((size_t)b * CCH + c0 + 8) * NT + n] = v1;
        }
    }
}

// ============================================================
// Flash attention — EXACT R7/R12 schedule (best measured: 147.9us).
// fp16 QK, bf16 PV, smem P, S-ahead pipeline, fused residual.
// grid (NT/64, B), 256 threads, 2 CTAs/SM.
// ============================================================
#define VTP 72
#define KPH 40
#define PP  72
#define OFF_VT 0
#define VT_BUF 36864
#define OFF_KS 73728
#define KS_BUF 5120
#define OFF_PS (OFF_KS + 3 * KS_BUF)
#define OFF_RS (OFF_PS + 9216)
#define SMEM_ATTN (OFF_RS + 512)

__global__ __launch_bounds__(256, 2) void attn_kernel(
    const float* __restrict__ x, const float* __restrict__ gammap,
    float* __restrict__ out)
{
    extern __shared__ char smc[];
    const uint32_t sb32 = smem_u32(smc);
    const int tid = threadIdx.x;
    const int w = tid >> 5, lane = tid & 31;
    const int g = lane >> 2, t = lane & 3;
    const int b = blockIdx.y;
    const int m0 = blockIdx.x * 64;

    const int qrow  = (w & 3) * 16;   // QK row group
    const int khalf = (w >> 2);       // QK key half (32 keys)
    const int mr0 = (w >> 2) * 32;    // PV row group
    const int cr  = (w & 3) * 64;     // PV col group

    const int a_row  = lane & 15;
    const int a_koff = (lane >> 4) * 8;
    const int b_c    = ((lane >> 4) & 1) * 8 + (lane & 7);
    const int b_koff = ((lane >> 3) & 1) * 8;

    // Q A-fragments (fp16 m16n8k16)
    uint32_t qa[2][4];
    {
        const __half* q = g_f + ((size_t)b * NT + m0 + qrow) * CQ;
#pragma unroll
        for (int kc = 0; kc < 2; kc++) {
            qa[kc][0] = *(const uint32_t*)&q[(size_t)g * CQ + kc * 16 + 2 * t];
            qa[kc][1] = *(const uint32_t*)&q[(size_t)(g + 8) * CQ + kc * 16 + 2 * t];
            qa[kc][2] = *(const uint32_t*)&q[(size_t)g * CQ + kc * 16 + 2 * t + 8];
            qa[kc][3] = *(const uint32_t*)&q[(size_t)(g + 8) * CQ + kc * 16 + 2 * t + 8];
        }
    }

    const __half* kg = g_g + (size_t)b * NT * CQ;
    const __nv_bfloat16* vg = g_h + (size_t)b * CCH * NT;
    const int krow = tid >> 2, kseg = tid & 3;

    // ---- prologue: K0->kbuf0, K1->kbuf1, V0->vbuf0 ----
    {
        cpa(sb32 + OFF_KS + krow * (KPH * 2) + kseg * 16,
            kg + (size_t)krow * CQ + kseg * 8);
        cpa(sb32 + OFF_KS + KS_BUF + krow * (KPH * 2) + kseg * 16,
            kg + (size_t)(64 + krow) * CQ + kseg * 8);
#pragma unroll
        for (int it = 0; it < 8; it++) {
            int idx = tid + it * 256;
            int c = idx >> 3, ch = idx & 7;
            cpa(sb32 + OFF_VT + (c * VTP + ch * 8) * 2, vg + (size_t)c * NT + ch * 8);
        }
        CP_COMMIT();
    }

    float acc[2][8][4];
#pragma unroll
    for (int mt = 0; mt < 2; mt++)
#pragma unroll
        for (int nt = 0; nt < 8; nt++)
#pragma unroll
            for (int r = 0; r < 4; r++) acc[mt][nt][r] = 0.f;
    float rsum0 = 0.f, rsum1 = 0.f;
    float s[4][4];

    CP_WAIT0();
    __syncthreads();

    // ---- QK(0) ----
    {
        const __half* Ks = (const __half*)(smc + OFF_KS);
#pragma unroll
        for (int nt = 0; nt < 4; nt++) {
#pragma unroll
            for (int r = 0; r < 4; r++) s[nt][r] = 0.f;
            const __half* kr = Ks + (khalf * 32 + nt * 8 + g) * KPH;
#pragma unroll
            for (int kc = 0; kc < 2; kc++) {
                uint32_t b0 = *(const uint32_t*)&kr[kc * 16 + 2 * t];
                uint32_t b1 = *(const uint32_t*)&kr[kc * 16 + 2 * t + 8];
                mma_f16(s[nt], qa[kc], b0, b1);
            }
        }
    }

#pragma unroll 1
    for (int kt = 0; kt < 64; kt++) {
        const int buf = kt & 1;
        __syncthreads();   // B1

        // prefetch V(kt+1), K(kt+2)
        if (kt + 1 < 64) {
            const int n0 = (kt + 1) * 64;
            const uint32_t VA = sb32 + OFF_VT + (1 - buf) * VT_BUF;
#pragma unroll
            for (int it = 0; it < 8; it++) {
                int idx = tid + it * 256;
                int c = idx >> 3, ch = idx & 7;
                cpa(VA + (c * VTP + ch * 8) * 2, vg + (size_t)c * NT + n0 + ch * 8);
            }
        }
        if (kt + 2 < 64) {
            const uint32_t KA = sb32 + OFF_KS + ((kt + 2) % 3) * KS_BUF;
            cpa(KA + krow * (KPH * 2) + kseg * 16,
                kg + (size_t)((kt + 2) * 64 + krow) * CQ + kseg * 8);
        }
        CP_COMMIT();

        // ---- exp(S(kt)) -> bf16 P ----
        {
            __nv_bfloat16* Ps = (__nv_bfloat16*)(smc + OFF_PS);
#pragma unroll
            for (int nt = 0; nt < 4; nt++) {
                float p0 = __expf(s[nt][0]);
                float p1 = __expf(s[nt][1]);
                float p2 = __expf(s[nt][2]);
                float p3 = __expf(s[nt][3]);
                rsum0 += p0 + p1;
                rsum1 += p2 + p3;
                int col = khalf * 32 + nt * 8 + 2 * t;
                *(__nv_bfloat162*)&Ps[(qrow + g) * PP + col] = __floats2bfloat162_rn(p0, p1);
                *(__nv_bfloat162*)&Ps[(qrow + 8 + g) * PP + col] = __floats2bfloat162_rn(p2, p3);
            }
        }

        CP_WAIT1();
        __syncthreads();   // B2: P(kt) + V(kt)/K(kt+1) visible

        // ---- QK(kt+1) ----
        if (kt + 1 < 64) {
            const __half* Ks = (const __half*)(smc + OFF_KS + ((kt + 1) % 3) * KS_BUF);
#pragma unroll
            for (int nt = 0; nt < 4; nt++) {
#pragma unroll
                for (int r = 0; r < 4; r++) s[nt][r] = 0.f;
                const __half* kr = Ks + (khalf * 32 + nt * 8 + g) * KPH;
#pragma unroll
                for (int kc = 0; kc < 2; kc++) {
                    uint32_t b0 = *(const uint32_t*)&kr[kc * 16 + 2 * t];
                    uint32_t b1 = *(const uint32_t*)&kr[kc * 16 + 2 * t + 8];
                    mma_f16(s[nt], qa[kc], b0, b1);
                }
            }
        }

        // ---- PV(kt) (bf16) ----
        const uint32_t PA = sb32 + OFF_PS;
        const uint32_t VA = sb32 + OFF_VT + buf * VT_BUF;
#pragma unroll
        for (int kc = 0; kc < 4; kc++) {
            uint32_t A0[4], A1[4];
            LDMX4(A0, PA + ((mr0 + a_row) * PP + kc * 16 + a_koff) * 2);
            LDMX4(A1, PA + ((mr0 + 16 + a_row) * PP + kc * 16 + a_koff) * 2);
#pragma unroll
            for (int np = 0; np < 4; np++) {
                uint32_t Bf[4];
                LDMX4(Bf, VA + ((cr + np * 16 + b_c) * VTP + kc * 16 + b_koff) * 2);
                mma_bf16(acc[0][np * 2],     A0, Bf[0], Bf[1]);
                mma_bf16(acc[0][np * 2 + 1], A0, Bf[2], Bf[3]);
                mma_bf16(acc[1][np * 2],     A1, Bf[0], Bf[1]);
                mma_bf16(acc[1][np * 2 + 1], A1, Bf[2], Bf[3]);
            }
        }
    }

    // ---- row sums: reduce over t lanes, combine the 2 key-half warps ----
    rsum0 += __shfl_xor_sync(0xffffffffu, rsum0, 1);
    rsum0 += __shfl_xor_sync(0xffffffffu, rsum0, 2);
    rsum1 += __shfl_xor_sync(0xffffffffu, rsum1, 1);
    rsum1 += __shfl_xor_sync(0xffffffffu, rsum1, 2);
    float* rs = (float*)(smc + OFF_RS);
    __syncthreads();
    if (t == 0) {
        rs[khalf * 64 + qrow + g] = rsum0;
        rs[khalf * 64 + qrow + 8 + g] = rsum1;
    }
    __syncthreads();

    // ---- epilogue: scale + residual ----
    const float gamma = gammap[0];
#pragma unroll
    for (int mt = 0; mt < 2; mt++) {
        int rg  = mr0 + mt * 16 + g;
        int rg8 = rg + 8;
        float s0 = gamma / (rs[rg]  + rs[64 + rg]);
        float s8 = gamma / (rs[rg8] + rs[64 + rg8]);
#pragma unroll
        for (int nt = 0; nt < 8; nt++) {
            int c = cr + nt * 8 + 2 * t;
            size_t gi0 = ((size_t)b * CCH + c) * NT + m0 + rg;
            size_t gi1 = gi0 + NT;
            size_t gj0 = ((size_t)b * CCH + c) * NT + m0 + rg8;
            size_t gj1 = gj0 + NT;
            out[gi0] = acc[mt][nt][0] * s0 + x[gi0];
            out[gi1] = acc[mt][nt][1] * s0 + x[gi1];
            out[gj0] = acc[mt][nt][2] * s8 + x[gj0];
            out[gj1] = acc[mt][nt][3] * s8 + x[gj1];
        }
    }
}

// ============================================================
extern "C" void kernel_launch(void* const* d_in, const int* in_sizes, int n_in,
                              void* d_out, int out_size)
{
    const float* x  = (const float*)d_in[0];
    const float* Wf = (const float*)d_in[1];
    const float* bf = (const float*)d_in[2];
    const float* Wg = (const float*)d_in[3];
    const float* bg = (const float*)d_in[4];
    const float* Wh = (const float*)d_in[5];
    const float* bh = (const float*)d_in[6];
    const float* gm = (const float*)d_in[7];
    float* out = (float*)d_out;

    cudaFuncSetAttribute(proj_kernel, cudaFuncAttributeMaxDynamicSharedMemorySize, SMEM_PROJ);
    dim3 gp(NT / 128, 5, BB);
    proj_kernel<<<gp, 256, SMEM_PROJ>>>(x, Wf, bf, Wg, bg, Wh, bh);

    cudaFuncSetAttribute(attn_kernel, cudaFuncAttributeMaxDynamicSharedMemorySize, SMEM_ATTN);
    dim3 ga(NT / 64, BB);
    attn_kernel<<<ga, 256, SMEM_ATTN>>>(x, gm, out);
}

// round 17
// speedup vs baseline: 1.0237x; 1.0017x over previous
#include <cuda_runtime.h>
#include <cuda_bf16.h>
#include <cuda_fp16.h>
#include <cstdint>
#include <cstddef>

#define BB 4
#define CCH 256
#define CQ 32
#define NT 4096

// ---- scratch (device globals; no allocation allowed) ----
__device__ __half g_f[BB * NT * CQ];                     // [b][n][o] (queries, fp16)
__device__ __half g_g[BB * NT * CQ];                     // [b][n][o] (keys, fp16)
__device__ __nv_bfloat16 g_h[(size_t)BB * CCH * NT];     // [b][c][n] (values, bf16)

__device__ __forceinline__ void mma_tf32(float* d, const uint32_t* a,
                                         uint32_t b0, uint32_t b1) {
    asm volatile(
        "mma.sync.aligned.m16n8k8.row.col.f32.tf32.tf32.f32 "
        "{%0,%1,%2,%3}, {%4,%5,%6,%7}, {%8,%9}, {%0,%1,%2,%3};"
        : "+f"(d[0]), "+f"(d[1]), "+f"(d[2]), "+f"(d[3])
        : "r"(a[0]), "r"(a[1]), "r"(a[2]), "r"(a[3]), "r"(b0), "r"(b1));
}
__device__ __forceinline__ void mma_f16(float* d, const uint32_t* a,
                                        uint32_t b0, uint32_t b1) {
    asm volatile(
        "mma.sync.aligned.m16n8k16.row.col.f32.f16.f16.f32 "
        "{%0,%1,%2,%3}, {%4,%5,%6,%7}, {%8,%9}, {%0,%1,%2,%3};"
        : "+f"(d[0]), "+f"(d[1]), "+f"(d[2]), "+f"(d[3])
        : "r"(a[0]), "r"(a[1]), "r"(a[2]), "r"(a[3]), "r"(b0), "r"(b1));
}
__device__ __forceinline__ void mma_bf16(float* d, const uint32_t* a,
                                         uint32_t b0, uint32_t b1) {
    asm volatile(
        "mma.sync.aligned.m16n8k16.row.col.f32.bf16.bf16.f32 "
        "{%0,%1,%2,%3}, {%4,%5,%6,%7}, {%8,%9}, {%0,%1,%2,%3};"
        : "+f"(d[0]), "+f"(d[1]), "+f"(d[2]), "+f"(d[3])
        : "r"(a[0]), "r"(a[1]), "r"(a[2]), "r"(a[3]), "r"(b0), "r"(b1));
}
#define LDMX4(r, addr) \
    asm volatile("ldmatrix.sync.aligned.m8n8.x4.shared.b16 {%0,%1,%2,%3}, [%4];" \
        : "=r"((r)[0]), "=r"((r)[1]), "=r"((r)[2]), "=r"((r)[3]) : "r"(addr))

__device__ __forceinline__ uint32_t smem_u32(const void* p) {
    uint32_t a;
    asm("{ .reg .u64 t; cvta.to.shared.u64 t, %1; cvt.u32.u64 %0, t; }" : "=r"(a) : "l"(p));
    return a;
}
__device__ __forceinline__ void cpa(uint32_t dst, const void* src) {
    asm volatile("cp.async.cg.shared.global [%0], [%1], 16;" :: "r"(dst), "l"(src));
}
#define CP_COMMIT() asm volatile("cp.async.commit_group;" ::: "memory")
#define CP_WAIT1()  asm volatile("cp.async.wait_group 1;" ::: "memory")
#define CP_WAIT0()  asm volatile("cp.async.wait_group 0;" ::: "memory")

// ============================================================
// Tensor-core projection (tf32 mma), k32 chunks,
// __launch_bounds__(256,4): 64-reg cap -> 4 CTAs/SM (measured ~23.6us).
// grid (NT/128, 5, B) = 640 CTAs.
// ============================================================
#define XP  136
#define WPD 36
#define XS_BUF (32 * XP * 4)
#define OFF_WS (2 * XS_BUF)
#define WS_BUF (64 * WPD * 4)
#define SMEM_PROJ (OFF_WS + 2 * WS_BUF)

__global__ __launch_bounds__(256, 4) void proj_kernel(
    const float* __restrict__ x,
    const float* __restrict__ Wf, const float* __restrict__ bf,
    const float* __restrict__ Wg, const float* __restrict__ bg,
    const float* __restrict__ Wh, const float* __restrict__ bh)
{
    extern __shared__ char smc[];
    const uint32_t sb32 = smem_u32(smc);
    const int tid = threadIdx.x;
    const int w = tid >> 5, lane = tid & 31;
    const int g = lane >> 2, t4 = lane & 3;
    const int b = blockIdx.z;
    const int rowbase = blockIdx.y * 64;
    const int n0 = blockIdx.x * 128;
    const int qr = (w & 3) * 16;
    const int nh = (w >> 2) * 64;

    {
        const uint32_t XA = sb32;
        const uint32_t WA = sb32 + OFF_WS;
#pragma unroll
        for (int it = 0; it < 4; it++) {
            int idx = tid + it * 256;
            int k = idx >> 5, nn = (idx & 31) * 4;
            cpa(XA + (k * XP + nn) * 4, x + ((size_t)b * CCH + k) * NT + n0 + nn);
        }
#pragma unroll
        for (int it = 0; it < 2; it++) {
            int idx = tid + it * 256;
            int m = idx >> 3, kk = (idx & 7) * 4;
            int rg = rowbase + m;
            const float* src;
            if (rg < 32)       src = Wf + rg * CCH;
            else if (rg < 64)  src = Wg + (rg - 32) * CCH;
            else               src = Wh + (rg - 64) * CCH;
            cpa(WA + (m * WPD + kk) * 4, src + kk);
        }
        CP_COMMIT();
    }

    float acc[8][4];
#pragma unroll
    for (int nf = 0; nf < 8; nf++)
#pragma unroll
        for (int r = 0; r < 4; r++) acc[nf][r] = 0.f;

#pragma unroll 1
    for (int c = 0; c < 8; c++) {
        __syncthreads();
        if (c + 1 < 8) {
            const int k0 = (c + 1) * 32;
            const uint32_t XA = sb32 + ((c + 1) & 1) * XS_BUF;
            const uint32_t WA = sb32 + OFF_WS + ((c + 1) & 1) * WS_BUF;
#pragma unroll
            for (int it = 0; it < 4; it++) {
                int idx = tid + it * 256;
                int k = idx >> 5, nn = (idx & 31) * 4;
                cpa(XA + (k * XP + nn) * 4, x + ((size_t)b * CCH + k0 + k) * NT + n0 + nn);
            }
#pragma unroll
            for (int it = 0; it < 2; it++) {
                int idx = tid + it * 256;
                int m = idx >> 3, kk = (idx & 7) * 4;
                int rg = rowbase + m;
                const float* src;
                if (rg < 32)       src = Wf + rg * CCH;
                else if (rg < 64)  src = Wg + (rg - 32) * CCH;
                else               src = Wh + (rg - 64) * CCH;
                cpa(WA + (m * WPD + kk) * 4, src + k0 + kk);
            }
            CP_COMMIT();
            CP_WAIT1();
        } else {
            CP_WAIT0();
        }
        __syncthreads();

        const float* Xb = (const float*)(smc + (c & 1) * XS_BUF);
        const float* Wb = (const float*)(smc + OFF_WS + (c & 1) * WS_BUF);
#pragma unroll
        for (int kc = 0; kc < 4; kc++) {
            uint32_t A[4];
            A[0] = __float_as_uint(Wb[(qr + g) * WPD + kc * 8 + t4]);
            A[1] = __float_as_uint(Wb[(qr + 8 + g) * WPD + kc * 8 + t4]);
            A[2] = __float_as_uint(Wb[(qr + g) * WPD + kc * 8 + t4 + 4]);
            A[3] = __float_as_uint(Wb[(qr + 8 + g) * WPD + kc * 8 + t4 + 4]);
#pragma unroll
            for (int nf = 0; nf < 8; nf++) {
                uint32_t b0 = __float_as_uint(Xb[(kc * 8 + t4) * XP + nh + nf * 8 + g]);
                uint32_t b1 = __float_as_uint(Xb[(kc * 8 + t4 + 4) * XP + nh + nf * 8 + g]);
                mma_tf32(acc[nf], A, b0, b1);
            }
        }
    }

    if (rowbase == 0) {
        const bool isf = (qr < 32);
        __half* dst = isf ? g_f : g_g;
        const float* bias = isf ? bf : bg;
        const int ob = isf ? qr : qr - 32;
        float bia0 = bias[ob + g], bia1 = bias[ob + 8 + g];
#pragma unroll
        for (int nf = 0; nf < 8; nf++) {
            int n = n0 + nh + nf * 8 + 2 * t4;
            size_t base0 = ((size_t)b * NT + n) * CQ;
            dst[base0 + ob + g]          = __float2half_rn(acc[nf][0] + bia0);
            dst[base0 + CQ + ob + g]     = __float2half_rn(acc[nf][1] + bia0);
            dst[base0 + ob + 8 + g]      = __float2half_rn(acc[nf][2] + bia1);
            dst[base0 + CQ + ob + 8 + g] = __float2half_rn(acc[nf][3] + bia1);
        }
    } else {
        int c0 = rowbase - 64 + qr + g;
        float bia0 = bh[c0], bia1 = bh[c0 + 8];
#pragma unroll
        for (int nf = 0; nf < 8; nf++) {
            int n = n0 + nh + nf * 8 + 2 * t4;
            __nv_bfloat162 v0 = __floats2bfloat162_rn(acc[nf][0] + bia0, acc[nf][1] + bia0);
            __nv_bfloat162 v1 = __floats2bfloat162_rn(acc[nf][2] + bia1, acc[nf][3] + bia1);
            *(__nv_bfloat162*)&g_h[((size_t)b * CCH + c0) * NT + n] = v0;
            *(__nv_bfloat162*)&g_h[((size_t)b * CCH + c0 + 8) * NT + n] = v1;
        }
    }
}

// ============================================================
// Flash attention — converged optimum (R7/R12/R14/R16 schedule).
// fp16 QK, bf16 PV, smem P, S-ahead pipeline, fused residual.
// grid (NT/64, B), 256 threads, 2 CTAs/SM.
// ============================================================
#define VTP 72
#define KPH 40
#define PP  72
#define OFF_VT 0
#define VT_BUF 36864
#define OFF_KS 73728
#define KS_BUF 5120
#define OFF_PS (OFF_KS + 3 * KS_BUF)
#define OFF_RS (OFF_PS + 9216)
#define SMEM_ATTN (OFF_RS + 512)

__global__ __launch_bounds__(256, 2) void attn_kernel(
    const float* __restrict__ x, const float* __restrict__ gammap,
    float* __restrict__ out)
{
    extern __shared__ char smc[];
    const uint32_t sb32 = smem_u32(smc);
    const int tid = threadIdx.x;
    const int w = tid >> 5, lane = tid & 31;
    const int g = lane >> 2, t = lane & 3;
    const int b = blockIdx.y;
    const int m0 = blockIdx.x * 64;

    const int qrow  = (w & 3) * 16;   // QK row group
    const int khalf = (w >> 2);       // QK key half (32 keys)
    const int mr0 = (w >> 2) * 32;    // PV row group
    const int cr  = (w & 3) * 64;     // PV col group

    const int a_row  = lane & 15;
    const int a_koff = (lane >> 4) * 8;
    const int b_c    = ((lane >> 4) & 1) * 8 + (lane & 7);
    const int b_koff = ((lane >> 3) & 1) * 8;

    // Q A-fragments (fp16 m16n8k16)
    uint32_t qa[2][4];
    {
        const __half* q = g_f + ((size_t)b * NT + m0 + qrow) * CQ;
#pragma unroll
        for (int kc = 0; kc < 2; kc++) {
            qa[kc][0] = *(const uint32_t*)&q[(size_t)g * CQ + kc * 16 + 2 * t];
            qa[kc][1] = *(const uint32_t*)&q[(size_t)(g + 8) * CQ + kc * 16 + 2 * t];
            qa[kc][2] = *(const uint32_t*)&q[(size_t)g * CQ + kc * 16 + 2 * t + 8];
            qa[kc][3] = *(const uint32_t*)&q[(size_t)(g + 8) * CQ + kc * 16 + 2 * t + 8];
        }
    }

    const __half* kg = g_g + (size_t)b * NT * CQ;
    const __nv_bfloat16* vg = g_h + (size_t)b * CCH * NT;
    const int krow = tid >> 2, kseg = tid & 3;

    // ---- prologue: K0->kbuf0, K1->kbuf1, V0->vbuf0 ----
    {
        cpa(sb32 + OFF_KS + krow * (KPH * 2) + kseg * 16,
            kg + (size_t)krow * CQ + kseg * 8);
        cpa(sb32 + OFF_KS + KS_BUF + krow * (KPH * 2) + kseg * 16,
            kg + (size_t)(64 + krow) * CQ + kseg * 8);
#pragma unroll
        for (int it = 0; it < 8; it++) {
            int idx = tid + it * 256;
            int c = idx >> 3, ch = idx & 7;
            cpa(sb32 + OFF_VT + (c * VTP + ch * 8) * 2, vg + (size_t)c * NT + ch * 8);
        }
        CP_COMMIT();
    }

    float acc[2][8][4];
#pragma unroll
    for (int mt = 0; mt < 2; mt++)
#pragma unroll
        for (int nt = 0; nt < 8; nt++)
#pragma unroll
            for (int r = 0; r < 4; r++) acc[mt][nt][r] = 0.f;
    float rsum0 = 0.f, rsum1 = 0.f;
    float s[4][4];

    CP_WAIT0();
    __syncthreads();

    // ---- QK(0) ----
    {
        const __half* Ks = (const __half*)(smc + OFF_KS);
#pragma unroll
        for (int nt = 0; nt < 4; nt++) {
#pragma unroll
            for (int r = 0; r < 4; r++) s[nt][r] = 0.f;
            const __half* kr = Ks + (khalf * 32 + nt * 8 + g) * KPH;
#pragma unroll
            for (int kc = 0; kc < 2; kc++) {
                uint32_t b0 = *(const uint32_t*)&kr[kc * 16 + 2 * t];
                uint32_t b1 = *(const uint32_t*)&kr[kc * 16 + 2 * t + 8];
                mma_f16(s[nt], qa[kc], b0, b1);
            }
        }
    }

#pragma unroll 1
    for (int kt = 0; kt < 64; kt++) {
        const int buf = kt & 1;
        __syncthreads();   // B1

        // prefetch V(kt+1), K(kt+2)
        if (kt + 1 < 64) {
            const int n0 = (kt + 1) * 64;
            const uint32_t VA = sb32 + OFF_VT + (1 - buf) * VT_BUF;
#pragma unroll
            for (int it = 0; it < 8; it++) {
                int idx = tid + it * 256;
                int c = idx >> 3, ch = idx & 7;
                cpa(VA + (c * VTP + ch * 8) * 2, vg + (size_t)c * NT + n0 + ch * 8);
            }
        }
        if (kt + 2 < 64) {
            const uint32_t KA = sb32 + OFF_KS + ((kt + 2) % 3) * KS_BUF;
            cpa(KA + krow * (KPH * 2) + kseg * 16,
                kg + (size_t)((kt + 2) * 64 + krow) * CQ + kseg * 8);
        }
        CP_COMMIT();

        // ---- exp(S(kt)) -> bf16 P ----
        {
            __nv_bfloat16* Ps = (__nv_bfloat16*)(smc + OFF_PS);
#pragma unroll
            for (int nt = 0; nt < 4; nt++) {
                float p0 = __expf(s[nt][0]);
                float p1 = __expf(s[nt][1]);
                float p2 = __expf(s[nt][2]);
                float p3 = __expf(s[nt][3]);
                rsum0 += p0 + p1;
                rsum1 += p2 + p3;
                int col = khalf * 32 + nt * 8 + 2 * t;
                *(__nv_bfloat162*)&Ps[(qrow + g) * PP + col] = __floats2bfloat162_rn(p0, p1);
                *(__nv_bfloat162*)&Ps[(qrow + 8 + g) * PP + col] = __floats2bfloat162_rn(p2, p3);
            }
        }

        CP_WAIT1();
        __syncthreads();   // B2: P(kt) + V(kt)/K(kt+1) visible

        // ---- QK(kt+1) ----
        if (kt + 1 < 64) {
            const __half* Ks = (const __half*)(smc + OFF_KS + ((kt + 1) % 3) * KS_BUF);
#pragma unroll
            for (int nt = 0; nt < 4; nt++) {
#pragma unroll
                for (int r = 0; r < 4; r++) s[nt][r] = 0.f;
                const __half* kr = Ks + (khalf * 32 + nt * 8 + g) * KPH;
#pragma unroll
                for (int kc = 0; kc < 2; kc++) {
                    uint32_t b0 = *(const uint32_t*)&kr[kc * 16 + 2 * t];
                    uint32_t b1 = *(const uint32_t*)&kr[kc * 16 + 2 * t + 8];
                    mma_f16(s[nt], qa[kc], b0, b1);
                }
            }
        }

        // ---- PV(kt) (bf16) ----
        const uint32_t PA = sb32 + OFF_PS;
        const uint32_t VA = sb32 + OFF_VT + buf * VT_BUF;
#pragma unroll
        for (int kc = 0; kc < 4; kc++) {
            uint32_t A0[4], A1[4];
            LDMX4(A0, PA + ((mr0 + a_row) * PP + kc * 16 + a_koff) * 2);
            LDMX4(A1, PA + ((mr0 + 16 + a_row) * PP + kc * 16 + a_koff) * 2);
#pragma unroll
            for (int np = 0; np < 4; np++) {
                uint32_t Bf[4];
                LDMX4(Bf, VA + ((cr + np * 16 + b_c) * VTP + kc * 16 + b_koff) * 2);
                mma_bf16(acc[0][np * 2],     A0, Bf[0], Bf[1]);
                mma_bf16(acc[0][np * 2 + 1], A0, Bf[2], Bf[3]);
                mma_bf16(acc[1][np * 2],     A1, Bf[0], Bf[1]);
                mma_bf16(acc[1][np * 2 + 1], A1, Bf[2], Bf[3]);
            }
        }
    }

    // ---- row sums: reduce over t lanes, combine the 2 key-half warps ----
    rsum0 += __shfl_xor_sync(0xffffffffu, rsum0, 1);
    rsum0 += __shfl_xor_sync(0xffffffffu, rsum0, 2);
    rsum1 += __shfl_xor_sync(0xffffffffu, rsum1, 1);
    rsum1 += __shfl_xor_sync(0xffffffffu, rsum1, 2);
    float* rs = (float*)(smc + OFF_RS);
    __syncthreads();
    if (t == 0) {
        rs[khalf * 64 + qrow + g] = rsum0;
        rs[khalf * 64 + qrow + 8 + g] = rsum1;
    }
    __syncthreads();

    // ---- epilogue: scale + residual ----
    const float gamma = gammap[0];
#pragma unroll
    for (int mt = 0; mt < 2; mt++) {
        int rg  = mr0 + mt * 16 + g;
        int rg8 = rg + 8;
        float s0 = gamma / (rs[rg]  + rs[64 + rg]);
        float s8 = gamma / (rs[rg8] + rs[64 + rg8]);
#pragma unroll
        for (int nt = 0; nt < 8; nt++) {
            int c = cr + nt * 8 + 2 * t;
            size_t gi0 = ((size_t)b * CCH + c) * NT + m0 + rg;
            size_t gi1 = gi0 + NT;
            size_t gj0 = ((size_t)b * CCH + c) * NT + m0 + rg8;
            size_t gj1 = gj0 + NT;
            out[gi0] = acc[mt][nt][0] * s0 + x[gi0];
            out[gi1] = acc[mt][nt][1] * s0 + x[gi1];
            out[gj0] = acc[mt][nt][2] * s8 + x[gj0];
            out[gj1] = acc[mt][nt][3] * s8 + x[gj1];
        }
    }
}

// ============================================================
extern "C" void kernel_launch(void* const* d_in, const int* in_sizes, int n_in,
                              void* d_out, int out_size)
{
    const float* x  = (const float*)d_in[0];
    const float* Wf = (const float*)d_in[1];
    const float* bf = (const float*)d_in[2];
    const float* Wg = (const float*)d_in[3];
    const float* bg = (const float*)d_in[4];
    const float* Wh = (const float*)d_in[5];
    const float* bh = (const float*)d_in[6];
    const float* gm = (const float*)d_in[7];
    float* out = (float*)d_out;

    cudaFuncSetAttribute(proj_kernel, cudaFuncAttributeMaxDynamicSharedMemorySize, SMEM_PROJ);
    dim3 gp(NT / 128, 5, BB);
    proj_kernel<<<gp, 256, SMEM_PROJ>>>(x, Wf, bf, Wg, bg, Wh, bh);

    cudaFuncSetAttribute(attn_kernel, cudaFuncAttributeMaxDynamicSharedMemorySize, SMEM_ATTN);
    dim3 ga(NT / 64, BB);
    attn_kernel<<<ga, 256, SMEM_ATTN>>>(x, gm, out);
}